// round 12
// baseline (speedup 1.0000x reference)
#include <cuda_runtime.h>

// Wealth_21182778704643 — GB300 sm_103a, R12
// R11 = 82.43us (DRAM 85.8%). R12 deletes the CTA-start block barrier:
//   - action staged per-warp (own t-row, producer==consumer, __syncwarp only)
//   - mu loaded into ONE register per thread at start; its STS + the only
//     __syncthreads happen AFTER the sigma loop (mu consumed in the epilogue)
// First sigma LDG now issues immediately at CTA start — removes the ~600cyc
// exposed staging bubble at each of the 7 wave starts.
// (R8 failed this via cp.async L1tex contention; R10 via +16 regs. This is +1 reg.)

#define B_DIM 64
#define T_DIM 512
#define N_DIM 64
#define M_DIM 64

#define TB 16                 // time steps per block (one warp each)
#define THREADS 512
#define CHUNKS (T_DIM / TB)   // 32 blocks per b
#define MU_PAD 17

__device__ float    g_partial[B_DIM * CHUNKS];  // overwritten every run
__device__ unsigned g_count[B_DIM];             // 0 at load; restored to 0 every run

__device__ __forceinline__ float k_dt()  { return 1.0f / 252.0f; }
__device__ __forceinline__ float k_pen() { return 0.5f * 0.1f * (1.0f / 252.0f); } // GAMMA/2*DT

__global__ __launch_bounds__(THREADS, 2)
void wealth_main_kernel(const float* __restrict__ action,
                        const float* __restrict__ mu,
                        const float* __restrict__ sigma,
                        const float* __restrict__ zeta,
                        const float* __restrict__ bt,
                        float* __restrict__ out)
{
    __shared__ float a_s[TB * N_DIM];        // action[b, t0:t0+TB, :]   4 KB
    __shared__ float mu_s[N_DIM * MU_PAD];   // mu[b, :, t0:t0+TB] padded
    __shared__ float red_s[TB];              // per-warp contributions

    const int b   = blockIdx.y;
    const int t0  = blockIdx.x * TB;
    const int tid = threadIdx.x;

    const int w    = tid >> 5;     // warp id = local time step 0..15
    const int lane = tid & 31;
    const int q    = lane & 15;    // m float4 group 0..15
    const int h    = lane >> 4;    // n half
    const int t    = t0 + w;

    // --- mu: one coalesced LDG per thread, value parked in a register;
    //     the STS + block barrier happen AFTER the sigma loop ---
    const int mun = tid >> 4;      // 0..31? no: 512/16 = 32.. need 0..63
    // 512 threads cover 64n x 16tl wrong at >>4 (gives 0..31 twice). Use explicit split:
    const int m_n  = tid >> 3;     // 0..63   (8 tl per n? no, TB=16) -- see below
    (void)mun; (void)m_n;
    // correct mapping: i = tid covers 512 of the 1024 mu elems; 2 per thread.
    const float* mp = mu + (size_t)b * N_DIM * T_DIM + t0;
    const int i0 = tid;                  // first element
    const int i1 = tid + THREADS;        // second element (THREADS=512, total 1024)
    const float muv0 = mp[(size_t)(i0 >> 4) * T_DIM + (i0 & 15)];
    const float muv1 = mp[(size_t)(i1 >> 4) * T_DIM + (i1 & 15)];

    // --- action: each warp stages only ITS OWN t-row (no block barrier) ---
    {
        const float* ar = action + ((size_t)b * T_DIM + t) * N_DIM;
        a_s[w * N_DIM + lane]      = ar[lane];
        a_s[w * N_DIM + 32 + lane] = ar[32 + lane];
    }
    __syncwarp();

    // --- hoisted independent loads: in flight during the whole sigma loop ---
    const float4 z   = ((const float4*)(zeta + ((size_t)b * T_DIM + t) * M_DIM))[q];
    const float  btv = __ldg(bt + t);

    // --- Stream sigma[b, t, h*32 + n', 4q..4q+3], n' = 0..31 ---
    const float4* sig4 = (const float4*)(sigma + (((size_t)b * T_DIM + t) * N_DIM) * M_DIM)
                         + (size_t)h * 32 * (M_DIM / 4) + q;
    const float4* ag4  = (const float4*)(a_s + w * N_DIM + h * 32);   // 128B-aligned

    float4 acc = make_float4(0.f, 0.f, 0.f, 0.f);
    #pragma unroll
    for (int n4 = 0; n4 < 8; ++n4) {
        const float4 av = ag4[n4];   // one LDS.128 covers 4 n's
        #pragma unroll
        for (int j = 0; j < 4; ++j) {
            const float  an = (j == 0) ? av.x : (j == 1) ? av.y : (j == 2) ? av.z : av.w;
            const float4 s  = sig4[(n4 * 4 + j) * (M_DIM / 4)];
            acc.x = fmaf(an, s.x, acc.x);
            acc.y = fmaf(an, s.y, acc.y);
            acc.z = fmaf(an, s.z, acc.z);
            acc.w = fmaf(an, s.w, acc.w);
        }
    }

    // --- now park mu into smem and take the ONLY block barrier ---
    mu_s[(i0 >> 4) * MU_PAD + (i0 & 15)] = muv0;
    mu_s[(i1 >> 4) * MU_PAD + (i1 & 15)] = muv1;

    // --- combine the two n-halves (acc complete over n before squaring) ---
    acc.x += __shfl_xor_sync(0xffffffffu, acc.x, 16);
    acc.y += __shfl_xor_sync(0xffffffffu, acc.y, 16);
    acc.z += __shfl_xor_sync(0xffffffffu, acc.z, 16);
    acc.w += __shfl_xor_sync(0xffffffffu, acc.w, 16);

    // --- (risk + zeta)^2 partial for this m-quad ---
    const float vx = acc.x + z.x;
    const float vy = acc.y + z.y;
    const float vz = acc.z + z.z;
    const float vw = acc.w + z.w;
    float sq = vx * vx + vy * vy + vz * vz + vw * vw;

    #pragma unroll
    for (int off = 8; off; off >>= 1)
        sq += __shfl_xor_sync(0xffffffffu, sq, off, 16);

    __syncthreads();   // mu_s visible block-wide

    // --- wealth dot partial: each lane covers n = h*32 + 2q, 2q+1 ---
    const int n0 = h * 32 + q * 2;
    float wp = fmaf(a_s[w * N_DIM + n0],      mu_s[n0 * MU_PAD + w],
                    a_s[w * N_DIM + n0 + 1] * mu_s[(n0 + 1) * MU_PAD + w]);
    #pragma unroll
    for (int off = 16; off; off >>= 1)
        wp += __shfl_xor_sync(0xffffffffu, wp, off);

    if (lane == 0) {
        const float rw = wp + btv;
        red_s[w] = k_dt() * rw - k_pen() * sq;
    }
    __syncthreads();   // red_s visible to warp 0; warps 1..15 are done after this

    if (w == 0) {
        // block partial: warp 0 reduces the 16 warp contributions
        float v = (lane < TB) ? red_s[lane] : 0.0f;
        #pragma unroll
        for (int off = 8; off; off >>= 1)
            v += __shfl_xor_sync(0xffffffffu, v, off, 16);

        unsigned old = 0;
        if (lane == 0) {
            g_partial[b * CHUNKS + blockIdx.x] = v;
            asm volatile("atom.acq_rel.gpu.add.u32 %0, [%1], %2;"
                         : "=r"(old)
                         : "l"(&g_count[b]), "r"(1u)
                         : "memory");
        }
        const unsigned last = __shfl_sync(0xffffffffu, (old == CHUNKS - 1) ? 1u : 0u, 0);

        if (last) {
            float p = __ldcg(&g_partial[b * CHUNKS + lane]);   // 32 partials
            #pragma unroll
            for (int off = 16; off; off >>= 1)
                p += __shfl_xor_sync(0xffffffffu, p, off);
            if (lane == 0) {
                out[b] = p;
                atomicExch(&g_count[b], 0u);   // restore invariant for next replay
            }
        }
    }
}

extern "C" void kernel_launch(void* const* d_in, const int* in_sizes, int n_in,
                              void* d_out, int out_size)
{
    const float* action = (const float*)d_in[0];  // (B, T, N)
    const float* mu     = (const float*)d_in[1];  // (B, N, T)
    const float* sigma  = (const float*)d_in[2];  // (B, T, N, M)
    const float* zeta   = (const float*)d_in[3];  // (B, T, M)
    const float* bt     = (const float*)d_in[4];  // (T, 1)
    float* out          = (float*)d_out;          // (B,)

    (void)in_sizes; (void)n_in; (void)out_size;

    dim3 grid(CHUNKS, B_DIM);
    wealth_main_kernel<<<grid, THREADS>>>(action, mu, sigma, zeta, bt, out);
}